// round 14
// baseline (speedup 1.0000x reference)
#include <cuda_runtime.h>

#define NPRIMES 168
#define TPB 512
#define GWARPS 12            // producer warps; warps 12-15 stream
#define CHUNK 32             // columns per chunk (1 warp-gather unit)
#define NCHUNKS 16384        // N / CHUNK
#define GRID 444             // 3 blocks/SM x 148 SMs = exactly one wave
#define MAXLOC 37            // max chunks per block = ceil(16384/444)
#define TABN (NPRIMES * 1000)

// Interleaved (kernel, bias) table: one LDG.64 fetches both values.
__device__ float2 g_tab[TABN];

// Per-prime magic-mod descriptor (compile-time, constant memory):
//  magic = floor(2^32/p)+1  ->  k % p == k - p*umulhi(k, magic)   (k < 2^20)
struct PInfo { unsigned magic; int p; };

#define PRIME_LIST \
 X(2) X(3) X(5) X(7) X(11) X(13) X(17) X(19) X(23) X(29) \
 X(31) X(37) X(41) X(43) X(47) X(53) X(59) X(61) X(67) X(71) \
 X(73) X(79) X(83) X(89) X(97) X(101) X(103) X(107) X(109) X(113) \
 X(127) X(131) X(137) X(139) X(149) X(151) X(157) X(163) X(167) X(173) \
 X(179) X(181) X(191) X(193) X(197) X(199) X(211) X(223) X(227) X(229) \
 X(233) X(239) X(241) X(251) X(257) X(263) X(269) X(271) X(277) X(281) \
 X(283) X(293) X(307) X(311) X(313) X(317) X(331) X(337) X(347) X(349) \
 X(353) X(359) X(367) X(373) X(379) X(383) X(389) X(397) X(401) X(409) \
 X(419) X(421) X(431) X(433) X(439) X(443) X(449) X(457) X(461) X(463) \
 X(467) X(479) X(487) X(491) X(499) X(503) X(509) X(521) X(523) X(541) \
 X(547) X(557) X(563) X(569) X(571) X(577) X(587) X(593) X(599) X(601) \
 X(607) X(613) X(617) X(619) X(631) X(641) X(643) X(647) X(653) X(659) \
 X(661) X(673) X(677) X(683) X(691) X(701) X(709) X(719) X(727) X(733) \
 X(739) X(743) X(751) X(757) X(761) X(769) X(773) X(787) X(797) X(809) \
 X(811) X(821) X(823) X(827) X(829) X(839) X(853) X(857) X(859) X(863) \
 X(877) X(881) X(883) X(887) X(907) X(911) X(919) X(929) X(937) X(941) \
 X(947) X(953) X(967) X(971) X(977) X(983) X(991) X(997)

__constant__ PInfo C_PI[NPRIMES] = {
#define X(p) { 0xFFFFFFFFu / (unsigned)(p) + 1u, (p) },
  PRIME_LIST
#undef X
};

__global__ __launch_bounds__(256)
void interleave_tab(const float* __restrict__ kern, const float* __restrict__ bias)
{
    int i = blockIdx.x * 256 + threadIdx.x;
    if (i < TABN) g_tab[i] = make_float2(kern[i], bias[i]);
}

__global__ __launch_bounds__(TPB, 3)
void bwl_prime_main(const float* __restrict__ x,
                    float* __restrict__ out,
                    int N, int B)
{
    __shared__ float2 wb_s[MAXLOC][CHUNK];   // write-once ring (no reuse!)
    __shared__ int    ready[MAXLOC];

    const int t    = threadIdx.x;
    const int wid  = t >> 5;
    const int lane = t & 31;
    const int b    = blockIdx.x;
    const size_t nv = (size_t)(N >> 2);

    // local chunk j <-> global chunk c = b + j*GRID
    const int nloc = (NCHUNKS - b + GRID - 1) / GRID;   // 36 or 37

    if (t < MAXLOC) ready[t] = 0;
    __syncthreads();

    if (wid < GWARPS) {
        // ========== PRODUCERS: 12 warps, staggered start ==========
        // Stagger lets early warps finish their first chunk on a lightly
        // loaded L1 -> stream ramps within ~3us instead of ~10.
        if (wid > 0) __nanosleep((unsigned)(wid * 800));

#pragma unroll
        for (int rep = 0; rep < 4; ++rep) {
            const int j = wid + rep * GWARPS;
            if (j >= nloc) break;
            const int c = b + j * GRID;
            const unsigned k = (unsigned)(c * CHUNK + lane);

            float w = 0.f, a = 0.f;
            const float2* __restrict__ row = g_tab;
#pragma unroll 8
            for (int i = 0; i < NPRIMES; ++i) {
                const PInfo pi = C_PI[i];
                int m = (int)(k - (unsigned)pi.p * __umulhi(k, pi.magic)); // k%p
                float2 e = __ldg(row + m);
                w += e.x; a += e.y;
                row += 1000;
            }
            wb_s[j][lane] = make_float2(w, a);

            __syncwarp();
            if (lane == 0) {
                unsigned fa = (unsigned)__cvta_generic_to_shared(&ready[j]);
                asm volatile("st.release.cta.shared.b32 [%0], %1;"
                             :: "r"(fa), "r"(1) : "memory");
            }
        }
        // producers retire; grid is one wave -> no queued blocks blocked
    } else {
        // ========== CONSUMERS: 4 warps, each owns a 16-row band ==========
        const int s    = wid - GWARPS;       // 0..3
        const int col4 = lane & 7;           // float4 column within chunk
        const int rb   = s * 16 + (lane >> 3) * 4;   // 4 rows per thread

        for (int j = 0; j < nloc; ++j) {
            {
                unsigned fa = (unsigned)__cvta_generic_to_shared(&ready[j]);
                int f;
                for (;;) {
                    asm volatile("ld.acquire.cta.shared.b32 %0, [%1];"
                                 : "=r"(f) : "r"(fa) : "memory");
                    if (f) break;
                    __nanosleep(64);
                }
            }

            const float2 q0 = wb_s[j][col4 * 4 + 0];
            const float2 q1 = wb_s[j][col4 * 4 + 1];
            const float2 q2 = wb_s[j][col4 * 4 + 2];
            const float2 q3 = wb_s[j][col4 * 4 + 3];

            const int c = b + j * GRID;
            const float4* __restrict__ xv = reinterpret_cast<const float4*>(x)
                                            + (size_t)rb * nv + (size_t)c * 8 + col4;
            float4* __restrict__       ov = reinterpret_cast<float4*>(out)
                                            + (size_t)rb * nv + (size_t)c * 8 + col4;

#pragma unroll
            for (int r = 0; r < 4; ++r) {
                float4 xi = __ldcs(xv);
                float4 o;
                o.x = fmaf(xi.x, q0.x, q0.y);
                o.y = fmaf(xi.y, q1.x, q1.y);
                o.z = fmaf(xi.z, q2.x, q2.y);
                o.w = fmaf(xi.w, q3.x, q3.y);
                __stcs(ov, o);
                xv += nv;
                ov += nv;
            }
        }
    }
}

extern "C" void kernel_launch(void* const* d_in, const int* in_sizes, int n_in,
                              void* d_out, int out_size)
{
    const float* x  = (const float*)d_in[0];   // (B, N) float32
    const float* kr = (const float*)d_in[1];   // (168, 1000) float32
    const float* br = (const float*)d_in[2];   // (168, 1000) float32
    float* out = (float*)d_out;

    const int N = 524288;
    const int B = 64;                          // fixed by problem shape

    interleave_tab<<<(TABN + 255) / 256, 256>>>(kr, br);

    bwl_prime_main<<<GRID, TPB>>>(x, out, N, B);
}

// round 15
// speedup vs baseline: 1.9738x; 1.9738x over previous
#include <cuda_runtime.h>

#define NPRIMES 168
#define TPB 128
#define COLS 128            // 1 column per thread
#define STRIDE 1024         // table row stride: 8192 B = exactly 64 L1 lines
#define TABN (NPRIMES * STRIDE)

// Interleaved (kernel, bias) table, rows padded to 128B-aligned stride:
// one LDG.64 fetches both values, and no warp-row access straddles an
// extra line from row misalignment.
__device__ float2 g_tab[TABN];

// Per-prime magic-mod descriptor (compile-time, constant memory):
//  magic = floor(2^32/p)+1  ->  k % p == k - p*umulhi(k, magic)   (k < 2^20)
struct PInfo { unsigned magic; int p; };

#define PRIME_LIST \
 X(2) X(3) X(5) X(7) X(11) X(13) X(17) X(19) X(23) X(29) \
 X(31) X(37) X(41) X(43) X(47) X(53) X(59) X(61) X(67) X(71) \
 X(73) X(79) X(83) X(89) X(97) X(101) X(103) X(107) X(109) X(113) \
 X(127) X(131) X(137) X(139) X(149) X(151) X(157) X(163) X(167) X(173) \
 X(179) X(181) X(191) X(193) X(197) X(199) X(211) X(223) X(227) X(229) \
 X(233) X(239) X(241) X(251) X(257) X(263) X(269) X(271) X(277) X(281) \
 X(283) X(293) X(307) X(311) X(313) X(317) X(331) X(337) X(347) X(349) \
 X(353) X(359) X(367) X(373) X(379) X(383) X(389) X(397) X(401) X(409) \
 X(419) X(421) X(431) X(433) X(439) X(443) X(449) X(457) X(461) X(463) \
 X(467) X(479) X(487) X(491) X(499) X(503) X(509) X(521) X(523) X(541) \
 X(547) X(557) X(563) X(569) X(571) X(577) X(587) X(593) X(599) X(601) \
 X(607) X(613) X(617) X(619) X(631) X(641) X(643) X(647) X(653) X(659) \
 X(661) X(673) X(677) X(683) X(691) X(701) X(709) X(719) X(727) X(733) \
 X(739) X(743) X(751) X(757) X(761) X(769) X(773) X(787) X(797) X(809) \
 X(811) X(821) X(823) X(827) X(829) X(839) X(853) X(857) X(859) X(863) \
 X(877) X(881) X(883) X(887) X(907) X(911) X(919) X(929) X(937) X(941) \
 X(947) X(953) X(967) X(971) X(977) X(983) X(991) X(997)

__constant__ PInfo C_PI[NPRIMES] = {
#define X(p) { 0xFFFFFFFFu / (unsigned)(p) + 1u, (p) },
  PRIME_LIST
#undef X
};

__global__ __launch_bounds__(256)
void interleave_tab(const float* __restrict__ kern, const float* __restrict__ bias)
{
    int i = blockIdx.x * 256 + threadIdx.x;     // over 168*1000 source entries
    if (i < NPRIMES * 1000) {
        int r = i / 1000;
        int j = i - r * 1000;
        g_tab[r * STRIDE + j] = make_float2(kern[i], bias[i]);
    }
}

__global__ __launch_bounds__(TPB, 16)
void bwl_prime_main(const float* __restrict__ x,
                    float* __restrict__ out,
                    int N, int B)
{
    __shared__ float w_s[COLS];
    __shared__ float b_s[COLS];

    const int t  = threadIdx.x;
    const int k0 = blockIdx.x * COLS;
    const unsigned k = (unsigned)(k0 + t);      // this thread's column

    // ---- Phase A: gather w/b, one column per thread ----
    // Lane-consecutive residues -> coalesced LDG.64, rows line-aligned.
    float w = 0.f, a = 0.f;
    const float2* __restrict__ row = g_tab;

#pragma unroll 8
    for (int i = 0; i < NPRIMES; ++i) {
        const PInfo pi = C_PI[i];               // uniform constant read
        int m = (int)(k - (unsigned)pi.p * __umulhi(k, pi.magic));  // k % p
        float2 e = __ldg(row + m);
        w += e.x; a += e.y;
        row += STRIDE;
    }

    w_s[t] = w;  b_s[t] = a;
    __syncthreads();

    // ---- Phase B: stream; 4 row-groups x 32 float4-columns, rows in pairs ----
    const int col4 = t & 31;                    // float4 column within block
    const int rpg  = B >> 2;                    // rows per group (16)
    const int rbeg = (t >> 5) * rpg;

    const float4 wv = *reinterpret_cast<const float4*>(&w_s[col4 * 4]);
    const float4 bv = *reinterpret_cast<const float4*>(&b_s[col4 * 4]);

    const size_t nv = (size_t)(N >> 2);
    const float4* __restrict__ xv = reinterpret_cast<const float4*>(x)
                                    + (size_t)rbeg * nv + (k0 >> 2) + col4;
    float4* __restrict__       ov = reinterpret_cast<float4*>(out)
                                    + (size_t)rbeg * nv + (k0 >> 2) + col4;

#pragma unroll 4
    for (int r = 0; r < rpg; r += 2) {
        // two independent DRAM loads in flight before any consumption
        float4 x0 = __ldcs(xv);
        float4 x1 = __ldcs(xv + nv);

        float4 o0, o1;
        o0.x = fmaf(x0.x, wv.x, bv.x);
        o0.y = fmaf(x0.y, wv.y, bv.y);
        o0.z = fmaf(x0.z, wv.z, bv.z);
        o0.w = fmaf(x0.w, wv.w, bv.w);
        o1.x = fmaf(x1.x, wv.x, bv.x);
        o1.y = fmaf(x1.y, wv.y, bv.y);
        o1.z = fmaf(x1.z, wv.z, bv.z);
        o1.w = fmaf(x1.w, wv.w, bv.w);

        __stcs(ov, o0);
        __stcs(ov + nv, o1);
        xv += 2 * nv;
        ov += 2 * nv;
    }
}

extern "C" void kernel_launch(void* const* d_in, const int* in_sizes, int n_in,
                              void* d_out, int out_size)
{
    const float* x  = (const float*)d_in[0];   // (B, N) float32
    const float* kr = (const float*)d_in[1];   // (168, 1000) float32
    const float* br = (const float*)d_in[2];   // (168, 1000) float32
    float* out = (float*)d_out;

    const int N = 524288;
    const int B = in_sizes[0] / N;             // 64

    interleave_tab<<<(NPRIMES * 1000 + 255) / 256, 256>>>(kr, br);

    const int grid = N / COLS;                 // 4096 blocks
    bwl_prime_main<<<grid, TPB>>>(x, out, N, B);
}